// round 17
// baseline (speedup 1.0000x reference)
#include <cuda_runtime.h>
#include <cuda_bf16.h>
#include <cstdint>
#include <cstddef>

constexpr int NN   = 10000;
constexpr int EE   = 320000;
constexpr int DIN  = 512;
constexpr int DOUT = 256;

// Row chunking for gather/tmp/combine overlap (chunk0 multiple of 64)
constexpr int CH0 = 5056;             // 79 GEMM row-blocks of 64
constexpr int CH1 = NN - CH0;         // 4944 -> 78 row-blocks (last partial)

// ---------------- scratch (__device__ globals; no allocs allowed) ----------
__device__ float g_h[(size_t)NN * DOUT];
__device__ float g_tmp[(size_t)NN * DOUT];
__device__ float g_invdeg[NN];
__device__ int   g_degi[NN];
__device__ int   g_off[NN];
__device__ int   g_cur[NN];
__device__ int   g_src[EE];
__device__ int   g_dst[EE];
__device__ int   g_csr[EE];
__device__ int   g_is64;

// bf16 hi/lo split operands (weights in natural [K][N] layout)
__device__ __nv_bfloat16 g_xhi[(size_t)NN * DIN],  g_xlo[(size_t)NN * DIN];
__device__ __nv_bfloat16 g_w0hi[DIN * DOUT],       g_w0lo[DIN * DOUT];
__device__ __nv_bfloat16 g_wl1hi[DOUT * DOUT],     g_wl1lo[DOUT * DOUT];
__device__ __nv_bfloat16 g_wr1hi[DOUT * DOUT],     g_wr1lo[DOUT * DOUT];
__device__ __nv_bfloat16 g_wl2hi[DOUT * DOUT],     g_wl2lo[DOUT * DOUT];
__device__ __nv_bfloat16 g_wr2hi[DOUT * DOUT],     g_wr2lo[DOUT * DOUT];
__device__ __nv_bfloat16 g_hhi[(size_t)NN * DOUT], g_hlo[(size_t)NN * DOUT];
__device__ __nv_bfloat16 g_mhi[(size_t)NN * DOUT], g_mlo[(size_t)NN * DOUT];
__device__ __nv_bfloat16 g_o1hi[(size_t)NN * DOUT], g_o1lo[(size_t)NN * DOUT];

// ---------------------------------------------------------------------------
// Edge-index dtype detection (int64 vs int32).
// ---------------------------------------------------------------------------
__global__ void detect_kernel(const int* __restrict__ raw) {
    int nz = 0;
    for (int i = threadIdx.x; i < 1024; i += blockDim.x)
        nz |= (raw[2 * i + 1] != 0);
    nz = __syncthreads_or(nz);
    if (threadIdx.x == 0) g_is64 = nz ? 0 : 1;
}

// Decode edge_index into int32 src/dst + in-degree histogram.
__global__ void decode_degi_kernel(const int* __restrict__ raw,
                                   int* __restrict__ src, int* __restrict__ dst,
                                   int* __restrict__ degi) {
    int e = blockIdx.x * blockDim.x + threadIdx.x;
    if (e >= EE) return;
    int s, d;
    if (g_is64) { s = raw[2 * e]; d = raw[2 * (EE + e)]; }
    else        { s = raw[e];     d = raw[EE + e]; }
    src[e] = s;
    dst[e] = d;
    atomicAdd(&degi[d], 1);
}

// ---------------------------------------------------------------------------
// bf16 hi/lo split of x and the five weight matrices (one launch).
// ---------------------------------------------------------------------------
__global__ void split_kernel(const float* __restrict__ x,  const float* __restrict__ W0,
                             const float* __restrict__ Wl1, const float* __restrict__ Wr1,
                             const float* __restrict__ Wl2, const float* __restrict__ Wr2) {
    constexpr int S0 = NN * DIN;
    constexpr int S1 = DIN * DOUT;
    constexpr int S2 = DOUT * DOUT;
    int i = blockIdx.x * blockDim.x + threadIdx.x;
    const float* src; __nv_bfloat16 *hi, *lo; int off;
    if      (i < S0)               { src = x;   hi = g_xhi;  lo = g_xlo;  off = i; }
    else if (i < S0 + S1)          { src = W0;  hi = g_w0hi; lo = g_w0lo; off = i - S0; }
    else if (i < S0 + S1 + S2)     { src = Wl1; hi = g_wl1hi; lo = g_wl1lo; off = i - S0 - S1; }
    else if (i < S0 + S1 + 2 * S2) { src = Wr1; hi = g_wr1hi; lo = g_wr1lo; off = i - S0 - S1 - S2; }
    else if (i < S0 + S1 + 3 * S2) { src = Wl2; hi = g_wl2hi; lo = g_wl2lo; off = i - S0 - S1 - 2 * S2; }
    else if (i < S0 + S1 + 4 * S2) { src = Wr2; hi = g_wr2hi; lo = g_wr2lo; off = i - S0 - S1 - 3 * S2; }
    else return;
    float v = src[off];
    __nv_bfloat16 h = __float2bfloat16(v);
    hi[off] = h;
    lo[off] = __float2bfloat16(v - __bfloat162float(h));
}

// ---------------------------------------------------------------------------
// Exclusive scan over degrees -> CSR offsets + cursors + invdeg (1 block).
// ---------------------------------------------------------------------------
__global__ void scan_kernel(const int* __restrict__ degi, int* __restrict__ off,
                            int* __restrict__ cur, float* __restrict__ invdeg) {
    __shared__ int part[256];
    const int t = threadIdx.x;
    const int CH = (NN + 255) / 256;
    const int s0 = t * CH;
    int sum = 0;
    for (int j = 0; j < CH; j++) { int i = s0 + j; if (i < NN) sum += degi[i]; }
    part[t] = sum;
    __syncthreads();
    for (int d = 1; d < 256; d <<= 1) {
        int v = (t >= d) ? part[t - d] : 0;
        __syncthreads();
        part[t] += v;
        __syncthreads();
    }
    int run = (t > 0) ? part[t - 1] : 0;
    for (int j = 0; j < CH; j++) {
        int i = s0 + j;
        if (i < NN) {
            off[i] = run; cur[i] = run;
            int d = degi[i]; run += d;
            invdeg[i] = 1.0f / fmaxf((float)d, 1.0f);
        }
    }
}

__global__ void fill_kernel(const int* __restrict__ src, const int* __restrict__ dst,
                            int* __restrict__ cur, int* __restrict__ csr) {
    int e = blockIdx.x * blockDim.x + threadIdx.x;
    if (e < EE) {
        int p = atomicAdd(&cur[dst[e]], 1);
        csr[p] = src[e];
    }
}

// ---------------------------------------------------------------------------
// CSR gather for node range [base, base+gridDim.x): one block per node.
// ---------------------------------------------------------------------------
__global__ void gather_kernel(const float* __restrict__ h,
                              const int* __restrict__ csr,
                              const int* __restrict__ off,
                              const int* __restrict__ degi,
                              const float* __restrict__ invdeg,
                              __nv_bfloat16* __restrict__ mhi,
                              __nv_bfloat16* __restrict__ mlo,
                              int base) {
    const int node = base + blockIdx.x;
    const int t = threadIdx.x;               // 0..63
    const int eb = off[node];
    const int n = degi[node];
    const float4* hp = (const float4*)h;
    float4 acc = make_float4(0.f, 0.f, 0.f, 0.f);
    int e = 0;
    for (; e + 4 <= n; e += 4) {
        int s0 = csr[eb + e + 0];
        int s1 = csr[eb + e + 1];
        int s2 = csr[eb + e + 2];
        int s3 = csr[eb + e + 3];
        float4 v0 = hp[(size_t)s0 * 64 + t];
        float4 v1 = hp[(size_t)s1 * 64 + t];
        float4 v2 = hp[(size_t)s2 * 64 + t];
        float4 v3 = hp[(size_t)s3 * 64 + t];
        acc.x += (v0.x + v1.x) + (v2.x + v3.x);
        acc.y += (v0.y + v1.y) + (v2.y + v3.y);
        acc.z += (v0.z + v1.z) + (v2.z + v3.z);
        acc.w += (v0.w + v1.w) + (v2.w + v3.w);
    }
    for (; e < n; e++) {
        int s = csr[eb + e];
        float4 v = hp[(size_t)s * 64 + t];
        acc.x += v.x; acc.y += v.y; acc.z += v.z; acc.w += v.w;
    }
    const float s = invdeg[node];
    float o[4] = {acc.x * s, acc.y * s, acc.z * s, acc.w * s};
    __nv_bfloat16 hi[4], lo[4];
#pragma unroll
    for (int j = 0; j < 4; j++) {
        hi[j] = __float2bfloat16(o[j]);
        lo[j] = __float2bfloat16(o[j] - __bfloat162float(hi[j]));
    }
    size_t p = (size_t)node * DOUT + t * 4;
    __nv_bfloat162 a, b;
    a.x = hi[0]; a.y = hi[1]; b.x = hi[2]; b.y = hi[3];
    *(__nv_bfloat162*)(mhi + p) = a; *(__nv_bfloat162*)(mhi + p + 2) = b;
    a.x = lo[0]; a.y = lo[1]; b.x = lo[2]; b.y = lo[3];
    *(__nv_bfloat162*)(mlo + p) = a; *(__nv_bfloat162*)(mlo + p + 2) = b;
}

// ---------------------------------------------------------------------------
// Tensor-core GEMM, bf16x3 with merged-operand stages (R14 core, unchanged).
// Block 64x64, 4 warps, BK=32, PIPE=3 (57 KB smem).
// ---------------------------------------------------------------------------
#define LDSM4(d0, d1, d2, d3, addr) \
    asm volatile("ldmatrix.sync.aligned.m8n8.x4.shared.b16 {%0,%1,%2,%3}, [%4];" \
        : "=r"(d0), "=r"(d1), "=r"(d2), "=r"(d3) : "r"(addr))
#define LDSM4T(d0, d1, d2, d3, addr) \
    asm volatile("ldmatrix.sync.aligned.m8n8.x4.trans.shared.b16 {%0,%1,%2,%3}, [%4];" \
        : "=r"(d0), "=r"(d1), "=r"(d2), "=r"(d3) : "r"(addr))
#define MMA16816(c, a, b0, b1) \
    asm volatile("mma.sync.aligned.m16n8k16.row.col.f32.bf16.bf16.f32 " \
        "{%0,%1,%2,%3}, {%4,%5,%6,%7}, {%8,%9}, {%0,%1,%2,%3};" \
        : "+f"(c[0]), "+f"(c[1]), "+f"(c[2]), "+f"(c[3]) \
        : "r"(a[0]), "r"(a[1]), "r"(a[2]), "r"(a[3]), "r"(b0), "r"(b1))
#define CPA16(dst, src, sz) \
    asm volatile("cp.async.cg.shared.global [%0], [%1], 16, %2;" \
        :: "r"(dst), "l"(src), "r"(sz))
#define CPA_COMMIT() asm volatile("cp.async.commit_group;")

constexpr int ASTR = 40;           // halfs; 80B row stride (conflict-free ldsm)
constexpr int WSTR = 72;           // halfs; 144B row stride (conflict-free ldsm)
constexpr int ABUF = 64 * ASTR;
constexpr int WBUF = 32 * WSTR;
constexpr int PIPE = 3;

template<int K, bool BIAS, bool ADD, bool RELU, bool RES, bool OUTS>
__global__ __launch_bounds__(128)
void gemm_mma(const __nv_bfloat16* __restrict__ Ahi, const __nv_bfloat16* __restrict__ Alo,
              const __nv_bfloat16* __restrict__ Whi, const __nv_bfloat16* __restrict__ Wlo,
              const float* __restrict__ bias, const float* __restrict__ add,
              const float* __restrict__ res,
              float* __restrict__ C, __nv_bfloat16* __restrict__ Chi,
              __nv_bfloat16* __restrict__ Clo, int M) {
    constexpr int NST = K / 32;
    __shared__ __align__(16) __nv_bfloat16 As[PIPE * 2 * ABUF];
    __shared__ __align__(16) __nv_bfloat16 Ws[PIPE * 2 * WBUF];

    const int tid = threadIdx.x, wid = tid >> 5, lane = tid & 31;
    const int row0 = blockIdx.y * 64, col0 = blockIdx.x * 64;
    const int mb = (wid & 1) * 32, nb = (wid >> 1) * 32;

    float acc[2][4][4];
#pragma unroll
    for (int mt = 0; mt < 2; mt++)
#pragma unroll
        for (int nt = 0; nt < 4; nt++)
#pragma unroll
            for (int r = 0; r < 4; r++) acc[mt][nt][r] = 0.f;

    const int arow = tid >> 2;
    const int achunk = (tid & 3) * 8;
    const int wk = tid >> 2;
    const int wn = (tid & 3) * 16;

    const uint32_t asu = (uint32_t)__cvta_generic_to_shared(As);
    const uint32_t wsu = (uint32_t)__cvta_generic_to_shared(Ws);

    const int r0g = row0 + arow, r1g = r0g + 32;
    const int sz0 = (r0g < M) ? 16 : 0, sz1 = (r1g < M) ? 16 : 0;
    const int r0c = (r0g < M) ? r0g : 0, r1c = (r1g < M) ? r1g : 0;

#define ISSUE(S, BUF) { \
        const int k0 = (S) * 32; \
        const uint32_t ah = asu + ((BUF) * 2 * ABUF) * 2; \
        const uint32_t al = ah + ABUF * 2; \
        const uint32_t wh = wsu + ((BUF) * 2 * WBUF) * 2; \
        const uint32_t wl = wh + WBUF * 2; \
        CPA16(ah + (arow * ASTR + achunk) * 2,        Ahi + (size_t)r0c * K + k0 + achunk, sz0); \
        CPA16(ah + ((arow + 32) * ASTR + achunk) * 2, Ahi + (size_t)r1c * K + k0 + achunk, sz1); \
        CPA16(al + (arow * ASTR + achunk) * 2,        Alo + (size_t)r0c * K + k0 + achunk, sz0); \
        CPA16(al + ((arow + 32) * ASTR + achunk) * 2, Alo + (size_t)r1c * K + k0 + achunk, sz1); \
        CPA16(wh + (wk * WSTR + wn) * 2,              Whi + (size_t)(k0 + wk) * DOUT + col0 + wn, 16); \
        CPA16(wh + (wk * WSTR + wn + 8) * 2,          Whi + (size_t)(k0 + wk) * DOUT + col0 + wn + 8, 16); \
        CPA16(wl + (wk * WSTR + wn) * 2,              Wlo + (size_t)(k0 + wk) * DOUT + col0 + wn, 16); \
        CPA16(wl + (wk * WSTR + wn + 8) * 2,          Wlo + (size_t)(k0 + wk) * DOUT + col0 + wn + 8, 16); \
        CPA_COMMIT(); \
    }

    ISSUE(0, 0);
    if (NST > 1) ISSUE(1, 1);

    const int r = lane & 7, selr = lane >> 3;
    const uint32_t aoff = (uint32_t)((mb + (selr & 1) * 8 + r) * ASTR + (selr >> 1) * 8) * 2;
    const uint32_t boff = (uint32_t)(((selr & 1) * 8 + r) * WSTR + nb + (selr >> 1) * 8) * 2;

    for (int s = 0; s < NST; s++) {
        if (s + 1 < NST) { asm volatile("cp.async.wait_group 1;"); }
        else             { asm volatile("cp.async.wait_group 0;"); }
        __syncthreads();
        if (s + 2 < NST) ISSUE(s + 2, (s + 2) % PIPE);

        const int buf = s % PIPE;
        const uint32_t ahb = asu + (buf * 2 * ABUF) * 2 + aoff;
        const uint32_t alb = ahb + ABUF * 2;
        const uint32_t whb = wsu + (buf * 2 * WBUF) * 2 + boff;
        const uint32_t wlb = whb + WBUF * 2;
#pragma unroll
        for (int kk = 0; kk < 32; kk += 16) {
            uint32_t ahr[2][4], alr[2][4], bh0[4], bh1[4], bl0[4], bl1[4];
            LDSM4(ahr[0][0], ahr[0][1], ahr[0][2], ahr[0][3], ahb + kk * 2);
            LDSM4(ahr[1][0], ahr[1][1], ahr[1][2], ahr[1][3], ahb + kk * 2 + 16 * ASTR * 2);
            LDSM4(alr[0][0], alr[0][1], alr[0][2], alr[0][3], alb + kk * 2);
            LDSM4(alr[1][0], alr[1][1], alr[1][2], alr[1][3], alb + kk * 2 + 16 * ASTR * 2);
            const uint32_t bhk = whb + kk * WSTR * 2;
            const uint32_t blk = wlb + kk * WSTR * 2;
            LDSM4T(bh0[0], bh0[1], bh0[2], bh0[3], bhk);
            LDSM4T(bh1[0], bh1[1], bh1[2], bh1[3], bhk + 16 * 2);
            LDSM4T(bl0[0], bl0[1], bl0[2], bl0[3], blk);
            LDSM4T(bl1[0], bl1[1], bl1[2], bl1[3], blk + 16 * 2);
#pragma unroll
            for (int mt = 0; mt < 2; mt++) {
                MMA16816(acc[mt][0], ahr[mt], bh0[0], bh0[1]);
                MMA16816(acc[mt][1], ahr[mt], bh0[2], bh0[3]);
                MMA16816(acc[mt][2], ahr[mt], bh1[0], bh1[1]);
                MMA16816(acc[mt][3], ahr[mt], bh1[2], bh1[3]);
                MMA16816(acc[mt][0], alr[mt], bh0[0], bh0[1]);
                MMA16816(acc[mt][1], alr[mt], bh0[2], bh0[3]);
                MMA16816(acc[mt][2], alr[mt], bh1[0], bh1[1]);
                MMA16816(acc[mt][3], alr[mt], bh1[2], bh1[3]);
                MMA16816(acc[mt][0], ahr[mt], bl0[0], bl0[1]);
                MMA16816(acc[mt][1], ahr[mt], bl0[2], bl0[3]);
                MMA16816(acc[mt][2], ahr[mt], bl1[0], bl1[1]);
                MMA16816(acc[mt][3], ahr[mt], bl1[2], bl1[3]);
            }
        }
    }
#undef ISSUE

    // epilogue: [+bias] [+add] [relu] [+res]
    const int g = lane >> 2, tig = lane & 3;
#pragma unroll
    for (int mt = 0; mt < 2; mt++) {
#pragma unroll
        for (int half = 0; half < 2; half++) {
            const int row = row0 + mb + mt * 16 + g + half * 8;
            if (row >= M) continue;
#pragma unroll
            for (int nt = 0; nt < 4; nt++) {
                const int col = col0 + nb + nt * 8 + tig * 2;
                float v0 = acc[mt][nt][half * 2 + 0];
                float v1 = acc[mt][nt][half * 2 + 1];
                if (BIAS) { v0 += bias[col]; v1 += bias[col + 1]; }
                if (ADD) {
                    float2 aa = *(const float2*)(add + (size_t)row * DOUT + col);
                    v0 += aa.x; v1 += aa.y;
                }
                if (RELU) { v0 = fmaxf(v0, 0.f); v1 = fmaxf(v1, 0.f); }
                if (RES) {
                    float2 rr = *(const float2*)(res + (size_t)row * DOUT + col);
                    v0 += rr.x; v1 += rr.y;
                }
                float2 o; o.x = v0; o.y = v1;
                *(float2*)(C + (size_t)row * DOUT + col) = o;
                if (OUTS) {
                    __nv_bfloat16 h0 = __float2bfloat16(v0), h1 = __float2bfloat16(v1);
                    __nv_bfloat162 hh; hh.x = h0; hh.y = h1;
                    *(__nv_bfloat162*)(Chi + (size_t)row * DOUT + col) = hh;
                    __nv_bfloat162 ll;
                    ll.x = __float2bfloat16(v0 - __bfloat162float(h0));
                    ll.y = __float2bfloat16(v1 - __bfloat162float(h1));
                    *(__nv_bfloat162*)(Clo + (size_t)row * DOUT + col) = ll;
                }
            }
        }
    }
}

// ---------------------------------------------------------------------------
// Launch graph (triple-stream):
//   main: split gemm1 | tmp1a tmp1b | (wait eO1) tmp2a tmp2b | (wait eEnd)
//   s2:   detect decode scan fill | gather1a gather1b | gather2a gather2b
//   s3:   c1a c1b (=out1, eO1) | c2a c2b (=out2, eEnd)
// ---------------------------------------------------------------------------
extern "C" void kernel_launch(void* const* d_in, const int* in_sizes, int n_in,
                              void* d_out, int out_size) {
    const float* x   = (const float*)d_in[0];
    const int*   ei  = (const int*)d_in[1];
    const float* W0  = (const float*)d_in[2];
    const float* b0  = (const float*)d_in[3];
    const float* Wl1 = (const float*)d_in[4];
    const float* bl1 = (const float*)d_in[5];
    const float* Wr1 = (const float*)d_in[6];
    const float* Wl2 = (const float*)d_in[7];
    const float* bl2 = (const float*)d_in[8];
    const float* Wr2 = (const float*)d_in[9];

    float* out1 = (float*)d_out;
    float* out2 = out1 + (size_t)NN * DOUT;

    float *h, *tmp, *invdeg;
    int *degi, *off, *cur, *src, *dst, *csr;
    __nv_bfloat16 *xhi, *xlo, *w0hi, *w0lo, *wl1hi, *wl1lo, *wr1hi, *wr1lo;
    __nv_bfloat16 *wl2hi, *wl2lo, *wr2hi, *wr2lo, *hhi, *hlo, *mhi, *mlo, *o1hi, *o1lo;
    cudaGetSymbolAddress((void**)&h,      g_h);
    cudaGetSymbolAddress((void**)&tmp,    g_tmp);
    cudaGetSymbolAddress((void**)&invdeg, g_invdeg);
    cudaGetSymbolAddress((void**)&degi,   g_degi);
    cudaGetSymbolAddress((void**)&off,    g_off);
    cudaGetSymbolAddress((void**)&cur,    g_cur);
    cudaGetSymbolAddress((void**)&src,    g_src);
    cudaGetSymbolAddress((void**)&dst,    g_dst);
    cudaGetSymbolAddress((void**)&csr,    g_csr);
    cudaGetSymbolAddress((void**)&xhi,   g_xhi);   cudaGetSymbolAddress((void**)&xlo,   g_xlo);
    cudaGetSymbolAddress((void**)&w0hi,  g_w0hi);  cudaGetSymbolAddress((void**)&w0lo,  g_w0lo);
    cudaGetSymbolAddress((void**)&wl1hi, g_wl1hi); cudaGetSymbolAddress((void**)&wl1lo, g_wl1lo);
    cudaGetSymbolAddress((void**)&wr1hi, g_wr1hi); cudaGetSymbolAddress((void**)&wr1lo, g_wr1lo);
    cudaGetSymbolAddress((void**)&wl2hi, g_wl2hi); cudaGetSymbolAddress((void**)&wl2lo, g_wl2lo);
    cudaGetSymbolAddress((void**)&wr2hi, g_wr2hi); cudaGetSymbolAddress((void**)&wr2lo, g_wr2lo);
    cudaGetSymbolAddress((void**)&hhi,   g_hhi);   cudaGetSymbolAddress((void**)&hlo,   g_hlo);
    cudaGetSymbolAddress((void**)&mhi,   g_mhi);   cudaGetSymbolAddress((void**)&mlo,   g_mlo);
    cudaGetSymbolAddress((void**)&o1hi,  g_o1hi);  cudaGetSymbolAddress((void**)&o1lo,  g_o1lo);

    // Static streams + events (created on first, uncaptured call).
    static cudaStream_t s2 = nullptr, s3 = nullptr;
    static cudaEvent_t eH = nullptr, eG1a = nullptr, eG1b = nullptr;
    static cudaEvent_t eT1a = nullptr, eT1b = nullptr, eO1 = nullptr;
    static cudaEvent_t eG2a = nullptr, eG2b = nullptr;
    static cudaEvent_t eT2a = nullptr, eT2b = nullptr, eEnd = nullptr;
    if (!s2) {
        cudaStreamCreateWithFlags(&s2, cudaStreamNonBlocking);
        cudaStreamCreateWithFlags(&s3, cudaStreamNonBlocking);
        cudaEventCreateWithFlags(&eH,   cudaEventDisableTiming);
        cudaEventCreateWithFlags(&eG1a, cudaEventDisableTiming);
        cudaEventCreateWithFlags(&eG1b, cudaEventDisableTiming);
        cudaEventCreateWithFlags(&eT1a, cudaEventDisableTiming);
        cudaEventCreateWithFlags(&eT1b, cudaEventDisableTiming);
        cudaEventCreateWithFlags(&eO1,  cudaEventDisableTiming);
        cudaEventCreateWithFlags(&eG2a, cudaEventDisableTiming);
        cudaEventCreateWithFlags(&eG2b, cudaEventDisableTiming);
        cudaEventCreateWithFlags(&eT2a, cudaEventDisableTiming);
        cudaEventCreateWithFlags(&eT2b, cudaEventDisableTiming);
        cudaEventCreateWithFlags(&eEnd, cudaEventDisableTiming);
    }

    const int EB = (EE + 255) / 256;
    const int SPLIT_N = NN * DIN + DIN * DOUT + 4 * DOUT * DOUT;
    dim3 fgrid(DOUT / 64, (NN + 63) / 64);     // full GEMM: (4, 157)
    dim3 g0(DOUT / 64, CH0 / 64);              // chunk 0: (4, 79)
    dim3 g1(DOUT / 64, (CH1 + 63) / 64);       // chunk 1: (4, 78)
    const size_t O0 = (size_t)CH0 * DOUT;      // element offset of chunk 1

    // s2: edge decode + CSR build (off the critical path)
    detect_kernel<<<1, 256, 0, s2>>>(ei);
    cudaMemsetAsync(degi, 0, NN * sizeof(int), s2);
    decode_degi_kernel<<<EB, 256, 0, s2>>>(ei, src, dst, degi);
    scan_kernel<<<1, 256, 0, s2>>>(degi, off, cur, invdeg);
    fill_kernel<<<EB, 256, 0, s2>>>(src, dst, cur, csr);

    // main: split + gemm1 (h = x@W0 + b0)
    split_kernel<<<(SPLIT_N + 255) / 256, 256>>>(x, W0, Wl1, Wr1, Wl2, Wr2);
    gemm_mma<DIN, true, false, false, false, true><<<fgrid, 128>>>(
        xhi, xlo, w0hi, w0lo, b0, nullptr, nullptr, h, hhi, hlo, NN);
    cudaEventRecord(eH, 0);

    // ---- conv1 ----
    // s2: gather1 chunks (need full h + CSR)
    cudaStreamWaitEvent(s2, eH, 0);
    gather_kernel<<<CH0, 64, 0, s2>>>(h, csr, off, degi, invdeg, mhi, mlo, 0);
    cudaEventRecord(eG1a, s2);
    gather_kernel<<<CH1, 64, 0, s2>>>(h, csr, off, degi, invdeg, mhi, mlo, CH0);
    cudaEventRecord(eG1b, s2);

    // main: tmp1 = h@Wr1 in two row chunks
    gemm_mma<DOUT, false, false, false, false, false><<<g0, 128>>>(
        hhi, hlo, wr1hi, wr1lo, nullptr, nullptr, nullptr, tmp, nullptr, nullptr, CH0);
    cudaEventRecord(eT1a, 0);
    gemm_mma<DOUT, false, false, false, false, false><<<g1, 128>>>(
        hhi + O0, hlo + O0, wr1hi, wr1lo, nullptr, nullptr, nullptr,
        tmp + O0, nullptr, nullptr, CH1);
    cudaEventRecord(eT1b, 0);

    // s3: combine chunks (each waits on its tmp chunk + gather chunk)
    cudaStreamWaitEvent(s3, eT1a, 0);
    cudaStreamWaitEvent(s3, eG1a, 0);
    gemm_mma<DOUT, true, true, true, true, true><<<g0, 128, 0, s3>>>(
        mhi, mlo, wl1hi, wl1lo, bl1, tmp, h, out1, o1hi, o1lo, CH0);
    cudaStreamWaitEvent(s3, eT1b, 0);
    cudaStreamWaitEvent(s3, eG1b, 0);
    gemm_mma<DOUT, true, true, true, true, true><<<g1, 128, 0, s3>>>(
        mhi + O0, mlo + O0, wl1hi, wl1lo, bl1, tmp + O0, h + O0,
        out1 + O0, o1hi + O0, o1lo + O0, CH1);
    cudaEventRecord(eO1, s3);

    // ---- conv2 ----
    // s2: gather2 chunks (need complete out1)
    cudaStreamWaitEvent(s2, eO1, 0);
    gather_kernel<<<CH0, 64, 0, s2>>>(out1, csr, off, degi, invdeg, mhi, mlo, 0);
    cudaEventRecord(eG2a, s2);
    gather_kernel<<<CH1, 64, 0, s2>>>(out1, csr, off, degi, invdeg, mhi, mlo, CH0);
    cudaEventRecord(eG2b, s2);

    // main: tmp2 = out1@Wr2 in two row chunks (needs complete o1hi/o1lo)
    cudaStreamWaitEvent(0, eO1, 0);
    gemm_mma<DOUT, false, false, false, false, false><<<g0, 128>>>(
        o1hi, o1lo, wr2hi, wr2lo, nullptr, nullptr, nullptr, tmp, nullptr, nullptr, CH0);
    cudaEventRecord(eT2a, 0);
    gemm_mma<DOUT, false, false, false, false, false><<<g1, 128>>>(
        o1hi + O0, o1lo + O0, wr2hi, wr2lo, nullptr, nullptr, nullptr,
        tmp + O0, nullptr, nullptr, CH1);
    cudaEventRecord(eT2b, 0);

    // s3: combine chunks for out2
    cudaStreamWaitEvent(s3, eT2a, 0);
    cudaStreamWaitEvent(s3, eG2a, 0);
    gemm_mma<DOUT, true, true, false, true, false><<<g0, 128, 0, s3>>>(
        mhi, mlo, wl2hi, wl2lo, bl2, tmp, out1, out2, nullptr, nullptr, CH0);
    cudaStreamWaitEvent(s3, eT2b, 0);
    cudaStreamWaitEvent(s3, eG2b, 0);
    gemm_mma<DOUT, true, true, false, true, false><<<g1, 128, 0, s3>>>(
        mhi + O0, mlo + O0, wl2hi, wl2lo, bl2, tmp + O0, out1 + O0,
        out2 + O0, nullptr, nullptr, CH1);
    cudaEventRecord(eEnd, s3);

    // join all side-stream work back to the capture-origin stream
    cudaStreamWaitEvent(0, eEnd, 0);
}